// round 1
// baseline (speedup 1.0000x reference)
#include <cuda_runtime.h>
#include <cuda_fp16.h>
#include <cstdint>
#include <cstddef>

#define BB   16
#define LQL  2048
#define LKL  2048
#define DDIM 1024

#define BM 128
#define BN 128
#define BKC 64
#define AST 72      // BK + 8 pad (halves)  -> 144B row stride, conflict-free ldmatrix
#define VST 136     // BN + 8 pad (halves)  -> 272B row stride

// ---------------- scratch (static device globals; no runtime allocation) ----
__device__ __align__(16) __half g_Qh[(size_t)BB * LQL * DDIM];
__device__ __align__(16) __half g_Ql[(size_t)BB * LQL * DDIM];
__device__ __align__(16) __half g_Kh[(size_t)BB * LKL * DDIM];
__device__ __align__(16) __half g_Kl[(size_t)BB * LKL * DDIM];
__device__ __align__(16) __half g_V [(size_t)BB * LKL * DDIM];
__device__ __align__(16) float  g_S [(size_t)BB * LQL * LKL];
__device__ __align__(16) __half g_P [(size_t)BB * LQL * LKL];

// ---------------- small PTX helpers ----------------------------------------
__device__ __forceinline__ uint32_t s2u(const void* p) {
    return (uint32_t)__cvta_generic_to_shared(p);
}
__device__ __forceinline__ void ldm4(uint32_t* r, uint32_t a) {
    asm volatile("ldmatrix.sync.aligned.m8n8.x4.shared.b16 {%0,%1,%2,%3},[%4];"
                 : "=r"(r[0]), "=r"(r[1]), "=r"(r[2]), "=r"(r[3]) : "r"(a));
}
__device__ __forceinline__ void ldm4t(uint32_t* r, uint32_t a) {
    asm volatile("ldmatrix.sync.aligned.m8n8.x4.trans.shared.b16 {%0,%1,%2,%3},[%4];"
                 : "=r"(r[0]), "=r"(r[1]), "=r"(r[2]), "=r"(r[3]) : "r"(a));
}
__device__ __forceinline__ void mma_f16(float* c, const uint32_t* a, uint32_t b0, uint32_t b1) {
    asm volatile("mma.sync.aligned.m16n8k16.row.col.f32.f16.f16.f32 "
                 "{%0,%1,%2,%3},{%4,%5,%6,%7},{%8,%9},{%0,%1,%2,%3};"
                 : "+f"(c[0]), "+f"(c[1]), "+f"(c[2]), "+f"(c[3])
                 : "r"(a[0]), "r"(a[1]), "r"(a[2]), "r"(a[3]), "r"(b0), "r"(b1));
}
__device__ __forceinline__ void cpa16(uint32_t s, const void* g) {
    asm volatile("cp.async.cg.shared.global [%0],[%1],16;" :: "r"(s), "l"(g));
}
__device__ __forceinline__ void cpcommit() { asm volatile("cp.async.commit_group;"); }

// ---------------- conversion kernels ----------------------------------------
__global__ void cvt_split_kernel(const float4* __restrict__ x, int which, int n4) {
    int i = blockIdx.x * blockDim.x + threadIdx.x;
    if (i >= n4) return;
    __half* hi = which ? g_Kh : g_Qh;
    __half* lo = which ? g_Kl : g_Ql;
    float4 v = x[i];
    __half h0 = __float2half_rn(v.x), h1 = __float2half_rn(v.y);
    __half h2 = __float2half_rn(v.z), h3 = __float2half_rn(v.w);
    __half l0 = __float2half_rn(v.x - __half2float(h0));
    __half l1 = __float2half_rn(v.y - __half2float(h1));
    __half l2 = __float2half_rn(v.z - __half2float(h2));
    __half l3 = __float2half_rn(v.w - __half2float(h3));
    ((__half2*)hi)[2 * i]     = __halves2half2(h0, h1);
    ((__half2*)hi)[2 * i + 1] = __halves2half2(h2, h3);
    ((__half2*)lo)[2 * i]     = __halves2half2(l0, l1);
    ((__half2*)lo)[2 * i + 1] = __halves2half2(l2, l3);
}

__global__ void cvt_v_kernel(const float4* __restrict__ x, int n4) {
    int i = blockIdx.x * blockDim.x + threadIdx.x;
    if (i >= n4) return;
    float4 v = x[i];
    ((__half2*)g_V)[2 * i]     = __halves2half2(__float2half_rn(v.x), __float2half_rn(v.y));
    ((__half2*)g_V)[2 * i + 1] = __halves2half2(__float2half_rn(v.z), __float2half_rn(v.w));
}

// ---------------- GEMM1: S = Q K^T with fp16 hi/lo split (K=3*1024) ---------
__global__ __launch_bounds__(256)
void gemm_qk_kernel(const int* __restrict__ key_len) {
    int b  = blockIdx.z;
    int kl = key_len[b];
    int n0 = blockIdx.x * BN;
    if (n0 >= kl) return;            // masked tile (also kl==0): softmax never reads it
    int m0 = blockIdx.y * BM;

    extern __shared__ char smraw[];
    __half* As = (__half*)smraw;     // [2][BM][AST]
    __half* Bs = As + 2 * BM * AST;  // [2][BN][AST]

    int tid = threadIdx.x;
    const size_t qoff = ((size_t)b * LQL + m0) * DDIM;
    const size_t koff = ((size_t)b * LKL + n0) * DDIM;

    auto issue = [&](int t) {
        int ph = t >> 4;                    // 0:QhKh  1:QhKl  2:QlKh
        int k0 = (t & 15) * BKC;
        const __half* qa = (ph == 2) ? g_Ql : g_Qh;
        const __half* kb = (ph == 1) ? g_Kl : g_Kh;
        __half* as = As + (t & 1) * BM * AST;
        __half* bs = Bs + (t & 1) * BM * AST;
#pragma unroll
        for (int i = 0; i < 4; i++) {
            int idx = i * 256 + tid;
            int row = idx >> 3, ch = idx & 7;
            cpa16(s2u(as + row * AST + ch * 8), qa + qoff + (size_t)row * DDIM + k0 + ch * 8);
            cpa16(s2u(bs + row * AST + ch * 8), kb + koff + (size_t)row * DDIM + k0 + ch * 8);
        }
        cpcommit();
    };

    float acc[4][4][4];
#pragma unroll
    for (int mt = 0; mt < 4; mt++)
#pragma unroll
        for (int nt = 0; nt < 4; nt++)
#pragma unroll
            for (int j = 0; j < 4; j++) acc[mt][nt][j] = 0.0f;

    int lane = tid & 31, wid = tid >> 5;
    int wm = wid >> 2, wn = wid & 3;          // 2x4 warp grid, warp tile 64x32
    int arow  = lane & 15;
    int akoff = (lane >> 4) << 3;
    int g     = lane >> 3;
    int brow  = (lane & 7) + ((g >> 1) << 3);
    int bkoff = (g & 1) << 3;

    issue(0);
    const int KT = 48;
    for (int t = 0; t < KT; t++) {
        if (t + 1 < KT) { issue(t + 1); asm volatile("cp.async.wait_group 1;"); }
        else            { asm volatile("cp.async.wait_group 0;"); }
        __syncthreads();
        const __half* as = As + (t & 1) * BM * AST;
        const __half* bs = Bs + (t & 1) * BM * AST;
#pragma unroll
        for (int kk = 0; kk < BKC / 16; kk++) {
            uint32_t a[4][4], bf[4][2];
#pragma unroll
            for (int mt = 0; mt < 4; mt++)
                ldm4(a[mt], s2u(as + (wm * 64 + mt * 16 + arow) * AST + kk * 16 + akoff));
#pragma unroll
            for (int nt2 = 0; nt2 < 2; nt2++) {
                uint32_t r[4];
                ldm4(r, s2u(bs + (wn * 32 + nt2 * 16 + brow) * AST + kk * 16 + bkoff));
                bf[nt2 * 2][0] = r[0];     bf[nt2 * 2][1] = r[1];
                bf[nt2 * 2 + 1][0] = r[2]; bf[nt2 * 2 + 1][1] = r[3];
            }
#pragma unroll
            for (int mt = 0; mt < 4; mt++)
#pragma unroll
                for (int nt = 0; nt < 4; nt++)
                    mma_f16(acc[mt][nt], a[mt], bf[nt][0], bf[nt][1]);
        }
        __syncthreads();
    }

#pragma unroll
    for (int mt = 0; mt < 4; mt++) {
        int r0 = m0 + wm * 64 + mt * 16 + (lane >> 2);
#pragma unroll
        for (int nt = 0; nt < 4; nt++) {
            int c = n0 + wn * 32 + nt * 8 + (lane & 3) * 2;
            float* p0 = g_S + ((size_t)b * LQL + r0) * LKL + c;
            *(float2*)p0             = make_float2(acc[mt][nt][0], acc[mt][nt][1]);
            *(float2*)(p0 + 8 * LKL) = make_float2(acc[mt][nt][2], acc[mt][nt][3]);
        }
    }
}

// ---------------- row softmax with key_len mask ------------------------------
__global__ void softmax_kernel(const int* __restrict__ key_len) {
    int row = blockIdx.x;            // b*LQ + q
    int b = row >> 11;
    int kl = key_len[b];
    __half* prow = g_P + (size_t)row * LKL;
    int tid = threadIdx.x;

    if (kl == 0) {                   // all masked -> uniform softmax (matches jax exactly)
        __half2 u2 = __halves2half2(__float2half(1.0f / 2048.0f), __float2half(1.0f / 2048.0f));
        __half2* p2 = (__half2*)prow;
        for (int i = tid; i < LKL / 2; i += 256) p2[i] = u2;
        return;
    }

    const float* srow = g_S + (size_t)row * LKL;
    __shared__ float sh[LKL];
    __shared__ float red[256];

    float lmax = -3.4e38f;
    for (int k = tid; k < kl; k += 256) { float v = srow[k]; sh[k] = v; lmax = fmaxf(lmax, v); }
    red[tid] = lmax; __syncthreads();
    for (int s = 128; s > 0; s >>= 1) { if (tid < s) red[tid] = fmaxf(red[tid], red[tid + s]); __syncthreads(); }
    float m = red[0];
    __syncthreads();

    float lsum = 0.0f;
    for (int k = tid; k < kl; k += 256) { float e = __expf(sh[k] - m); sh[k] = e; lsum += e; }
    red[tid] = lsum; __syncthreads();
    for (int s = 128; s > 0; s >>= 1) { if (tid < s) red[tid] += red[tid + s]; __syncthreads(); }
    float inv = 1.0f / red[0];

    for (int k = tid; k < LKL; k += 256) {
        float p = (k < kl) ? sh[k] * inv : 0.0f;
        prow[k] = __float2half(p);
    }
}

// ---------------- GEMM2: O = P V ---------------------------------------------
__global__ __launch_bounds__(256)
void gemm_pv_kernel(float* __restrict__ out, const int* __restrict__ key_len) {
    int b  = blockIdx.z;
    int kl = key_len[b];
    int n0 = blockIdx.x * BN;        // over D (1024/128 = 8)
    int m0 = blockIdx.y * BM;

    extern __shared__ char smraw[];
    __half* As = (__half*)smraw;     // [2][BM][AST]   (P tile)
    __half* Vs = As + 2 * BM * AST;  // [2][64][VST]   (V tile, rows = k)

    int tid = threadIdx.x;

    auto issue = [&](int t) {
        int k0 = t * BKC;
        __half* as = As + (t & 1) * BM * AST;
        __half* vs = Vs + (t & 1) * 64 * VST;
#pragma unroll
        for (int i = 0; i < 4; i++) {
            int idx = i * 256 + tid;
            int row = idx >> 3, ch = idx & 7;
            cpa16(s2u(as + row * AST + ch * 8),
                  g_P + ((size_t)b * LQL + m0 + row) * LKL + k0 + ch * 8);
            int vrow = idx >> 4, vch = idx & 15;
            cpa16(s2u(vs + vrow * VST + vch * 8),
                  g_V + ((size_t)b * LKL + k0 + vrow) * DDIM + n0 + vch * 8);
        }
        cpcommit();
    };

    float acc[4][4][4];
#pragma unroll
    for (int mt = 0; mt < 4; mt++)
#pragma unroll
        for (int nt = 0; nt < 4; nt++)
#pragma unroll
            for (int j = 0; j < 4; j++) acc[mt][nt][j] = 0.0f;

    int lane = tid & 31, wid = tid >> 5;
    int wm = wid >> 2, wn = wid & 3;
    int arow  = lane & 15;
    int akoff = (lane >> 4) << 3;
    int g     = lane >> 3;
    int vkrow = (lane & 7) + ((g & 1) << 3);
    int vnoff = (g >> 1) << 3;

    int KT = (kl == 0) ? (LKL / BKC) : ((kl + BKC - 1) >> 6);   // P is 0 beyond kl

    issue(0);
    for (int t = 0; t < KT; t++) {
        if (t + 1 < KT) { issue(t + 1); asm volatile("cp.async.wait_group 1;"); }
        else            { asm volatile("cp.async.wait_group 0;"); }
        __syncthreads();
        const __half* as = As + (t & 1) * BM * AST;
        const __half* vs = Vs + (t & 1) * 64 * VST;
#pragma unroll
        for (int kk = 0; kk < BKC / 16; kk++) {
            uint32_t a[4][4], bf[4][2];
#pragma unroll
            for (int mt = 0; mt < 4; mt++)
                ldm4(a[mt], s2u(as + (wm * 64 + mt * 16 + arow) * AST + kk * 16 + akoff));
#pragma unroll
            for (int nt2 = 0; nt2 < 2; nt2++) {
                uint32_t r[4];
                ldm4t(r, s2u(vs + (kk * 16 + vkrow) * VST + wn * 32 + nt2 * 16 + vnoff));
                bf[nt2 * 2][0] = r[0];     bf[nt2 * 2][1] = r[1];
                bf[nt2 * 2 + 1][0] = r[2]; bf[nt2 * 2 + 1][1] = r[3];
            }
#pragma unroll
            for (int mt = 0; mt < 4; mt++)
#pragma unroll
                for (int nt = 0; nt < 4; nt++)
                    mma_f16(acc[mt][nt], a[mt], bf[nt][0], bf[nt][1]);
        }
        __syncthreads();
    }

#pragma unroll
    for (int mt = 0; mt < 4; mt++) {
        int r0 = m0 + wm * 64 + mt * 16 + (lane >> 2);
#pragma unroll
        for (int nt = 0; nt < 4; nt++) {
            int c = n0 + wn * 32 + nt * 8 + (lane & 3) * 2;
            float* p0 = out + ((size_t)b * LQL + r0) * DDIM + c;
            *(float2*)p0              = make_float2(acc[mt][nt][0], acc[mt][nt][1]);
            *(float2*)(p0 + 8 * DDIM) = make_float2(acc[mt][nt][2], acc[mt][nt][3]);
        }
    }
}

// ---------------- launch ------------------------------------------------------
extern "C" void kernel_launch(void* const* d_in, const int* in_sizes, int n_in,
                              void* d_out, int out_size) {
    const float* q  = (const float*)d_in[0];
    const float* k  = (const float*)d_in[1];
    const float* v  = (const float*)d_in[2];
    const int*   kl = (const int*)d_in[3];
    float* out = (float*)d_out;

    cudaFuncSetAttribute(gemm_qk_kernel, cudaFuncAttributeMaxDynamicSharedMemorySize, 73728);
    cudaFuncSetAttribute(gemm_pv_kernel, cudaFuncAttributeMaxDynamicSharedMemorySize, 71680);

    const int n4 = BB * LQL * DDIM / 4;   // 8388608
    cvt_split_kernel<<<n4 / 256, 256>>>((const float4*)q, 0, n4);
    cvt_split_kernel<<<n4 / 256, 256>>>((const float4*)k, 1, n4);
    cvt_v_kernel   <<<n4 / 256, 256>>>((const float4*)v, n4);

    gemm_qk_kernel<<<dim3(LKL / BN, LQL / BM, BB), 256, 73728>>>(kl);
    softmax_kernel<<<BB * LQL, 256>>>(kl);
    gemm_pv_kernel<<<dim3(DDIM / BN, LQL / BM, BB), 256, 71680>>>(out, kl);
}

// round 5
// speedup vs baseline: 1.0291x; 1.0291x over previous
#include <cuda_runtime.h>
#include <cuda_fp16.h>
#include <cstdint>
#include <cstddef>

#define BB   16
#define LQL  2048
#define LKL  2048
#define DDIM 1024

#define BM 128
#define BN 128
#define BKC 64
#define NS  3
#define AST 72      // BK + 8 pad (halves) -> 144B row stride, conflict-free ldmatrix
#define VST 136     // BN + 8 pad (halves) -> 272B row stride

#define QK_STAGE_H (2 * BM * AST)                  // halves per stage (A+B)
#define PV_STAGE_H (BM * AST + 64 * VST)
#define QK_SMEM (NS * QK_STAGE_H * 2)
#define PV_SMEM (NS * PV_STAGE_H * 2)

// ---------------- scratch (static device globals; no runtime allocation) ----
__device__ __align__(16) __half g_Qh[(size_t)BB * LQL * DDIM];
__device__ __align__(16) __half g_Ql[(size_t)BB * LQL * DDIM];
__device__ __align__(16) __half g_Kh[(size_t)BB * LKL * DDIM];
__device__ __align__(16) __half g_Kl[(size_t)BB * LKL * DDIM];
__device__ __align__(16) __half g_V [(size_t)BB * LKL * DDIM];
__device__ __align__(16) float  g_S [(size_t)BB * LQL * LKL];
__device__ __align__(16) __half g_P [(size_t)BB * LQL * LKL];

// ---------------- PTX helpers ------------------------------------------------
__device__ __forceinline__ uint32_t s2u(const void* p) {
    return (uint32_t)__cvta_generic_to_shared(p);
}
__device__ __forceinline__ void ldm4(uint32_t* r, uint32_t a) {
    asm volatile("ldmatrix.sync.aligned.m8n8.x4.shared.b16 {%0,%1,%2,%3},[%4];"
                 : "=r"(r[0]), "=r"(r[1]), "=r"(r[2]), "=r"(r[3]) : "r"(a));
}
__device__ __forceinline__ void ldm4t(uint32_t* r, uint32_t a) {
    asm volatile("ldmatrix.sync.aligned.m8n8.x4.trans.shared.b16 {%0,%1,%2,%3},[%4];"
                 : "=r"(r[0]), "=r"(r[1]), "=r"(r[2]), "=r"(r[3]) : "r"(a));
}
__device__ __forceinline__ void mma_f16(float* c, const uint32_t* a, uint32_t b0, uint32_t b1) {
    asm volatile("mma.sync.aligned.m16n8k16.row.col.f32.f16.f16.f32 "
                 "{%0,%1,%2,%3},{%4,%5,%6,%7},{%8,%9},{%0,%1,%2,%3};"
                 : "+f"(c[0]), "+f"(c[1]), "+f"(c[2]), "+f"(c[3])
                 : "r"(a[0]), "r"(a[1]), "r"(a[2]), "r"(a[3]), "r"(b0), "r"(b1));
}
__device__ __forceinline__ void cpa16(uint32_t s, const void* g) {
    asm volatile("cp.async.cg.shared.global [%0],[%1],16;" :: "r"(s), "l"(g));
}
__device__ __forceinline__ void cpcommit() { asm volatile("cp.async.commit_group;"); }

// ---------------- conversion kernels ----------------------------------------
__global__ void cvt_split_kernel(const float4* __restrict__ x, int which, int n4) {
    int i = blockIdx.x * blockDim.x + threadIdx.x;
    if (i >= n4) return;
    __half* hi = which ? g_Kh : g_Qh;
    __half* lo = which ? g_Kl : g_Ql;
    float4 v = x[i];
    __half h0 = __float2half_rn(v.x), h1 = __float2half_rn(v.y);
    __half h2 = __float2half_rn(v.z), h3 = __float2half_rn(v.w);
    __half l0 = __float2half_rn(v.x - __half2float(h0));
    __half l1 = __float2half_rn(v.y - __half2float(h1));
    __half l2 = __float2half_rn(v.z - __half2float(h2));
    __half l3 = __float2half_rn(v.w - __half2float(h3));
    ((__half2*)hi)[2 * i]     = __halves2half2(h0, h1);
    ((__half2*)hi)[2 * i + 1] = __halves2half2(h2, h3);
    ((__half2*)lo)[2 * i]     = __halves2half2(l0, l1);
    ((__half2*)lo)[2 * i + 1] = __halves2half2(l2, l3);
}

__global__ void cvt_v_kernel(const float4* __restrict__ x, int n4) {
    int i = blockIdx.x * blockDim.x + threadIdx.x;
    if (i >= n4) return;
    float4 v = x[i];
    ((__half2*)g_V)[2 * i]     = __halves2half2(__float2half_rn(v.x), __float2half_rn(v.y));
    ((__half2*)g_V)[2 * i + 1] = __halves2half2(__float2half_rn(v.z), __float2half_rn(v.w));
}

// ---------------- GEMM1: S = Q K^T with fp16 hi/lo split (K=3*1024) ---------
__global__ __launch_bounds__(256)
void gemm_qk_kernel(const int* __restrict__ key_len) {
    int b  = blockIdx.z;
    int kl = key_len[b];
    int n0 = blockIdx.x * BN;
    if (n0 >= kl) return;            // masked tile (also kl==0): softmax never reads it
    int m0 = blockIdx.y * BM;

    extern __shared__ __half sm[];

    int tid = threadIdx.x;
    const size_t qoff = ((size_t)b * LQL + m0) * DDIM;
    const size_t koff = ((size_t)b * LKL + n0) * DDIM;

    auto issue = [&](int t) {
        int ph = t >> 4;                    // 0:QhKh  1:QhKl  2:QlKh
        int k0 = (t & 15) * BKC;
        const __half* qa = ((ph == 2) ? g_Ql : g_Qh) + qoff + k0;
        const __half* kb = ((ph == 1) ? g_Kl : g_Kh) + koff + k0;
        __half* as = sm + (t % NS) * QK_STAGE_H;
        __half* bs = as + BM * AST;
#pragma unroll
        for (int i = 0; i < 4; i++) {
            int idx = i * 256 + tid;
            int row = idx >> 3, ch = idx & 7;
            cpa16(s2u(as + row * AST + ch * 8), qa + (size_t)row * DDIM + ch * 8);
            cpa16(s2u(bs + row * AST + ch * 8), kb + (size_t)row * DDIM + ch * 8);
        }
        cpcommit();
    };

    float acc[4][4][4];
#pragma unroll
    for (int mt = 0; mt < 4; mt++)
#pragma unroll
        for (int nt = 0; nt < 4; nt++)
#pragma unroll
            for (int j = 0; j < 4; j++) acc[mt][nt][j] = 0.0f;

    int lane = tid & 31, wid = tid >> 5;
    int wm = wid >> 2, wn = wid & 3;          // 2x4 warp grid, warp tile 64x32
    int arow  = lane & 15;
    int akoff = (lane >> 4) << 3;
    int g     = lane >> 3;
    int brow  = (lane & 7) + ((g >> 1) << 3);
    int bkoff = (g & 1) << 3;

    const int KT = 48;
    issue(0);
    issue(1);

    for (int s = 0; s < KT; s++) {
        if (s + 1 < KT) asm volatile("cp.async.wait_group 1;");
        else            asm volatile("cp.async.wait_group 0;");
        __syncthreads();
        if (s + 2 < KT) issue(s + 2);

        const __half* as = sm + (s % NS) * QK_STAGE_H;
        const __half* bs = as + BM * AST;
#pragma unroll
        for (int kk = 0; kk < BKC / 16; kk++) {
            uint32_t a[4][4], bf[4][2];
#pragma unroll
            for (int mt = 0; mt < 4; mt++)
                ldm4(a[mt], s2u(as + (wm * 64 + mt * 16 + arow) * AST + kk * 16 + akoff));
#pragma unroll
            for (int nt2 = 0; nt2 < 2; nt2++) {
                uint32_t r[4];
                ldm4(r, s2u(bs + (wn * 32 + nt2 * 16 + brow) * AST + kk * 16 + bkoff));
                bf[nt2 * 2][0] = r[0];     bf[nt2 * 2][1] = r[1];
                bf[nt2 * 2 + 1][0] = r[2]; bf[nt2 * 2 + 1][1] = r[3];
            }
#pragma unroll
            for (int mt = 0; mt < 4; mt++)
#pragma unroll
                for (int nt = 0; nt < 4; nt++)
                    mma_f16(acc[mt][nt], a[mt], bf[nt][0], bf[nt][1]);
        }
    }

#pragma unroll
    for (int mt = 0; mt < 4; mt++) {
        int r0 = m0 + wm * 64 + mt * 16 + (lane >> 2);
#pragma unroll
        for (int nt = 0; nt < 4; nt++) {
            int c = n0 + wn * 32 + nt * 8 + (lane & 3) * 2;
            float* p0 = g_S + ((size_t)b * LQL + r0) * LKL + c;
            *(float2*)p0             = make_float2(acc[mt][nt][0], acc[mt][nt][1]);
            *(float2*)(p0 + 8 * LKL) = make_float2(acc[mt][nt][2], acc[mt][nt][3]);
        }
    }
}

// ---------------- row softmax with key_len mask ------------------------------
__global__ void softmax_kernel(const int* __restrict__ key_len) {
    int row = blockIdx.x;            // b*LQ + q
    int b = row >> 11;
    int kl = key_len[b];
    __half* prow = g_P + (size_t)row * LKL;
    int tid = threadIdx.x;

    if (kl == 0) {                   // all masked -> uniform softmax (matches jax exactly)
        __half2 u2 = __halves2half2(__float2half(1.0f / 2048.0f), __float2half(1.0f / 2048.0f));
        __half2* p2 = (__half2*)prow;
        for (int i = tid; i < LKL / 2; i += 256) p2[i] = u2;
        return;
    }

    const float* srow = g_S + (size_t)row * LKL;
    __shared__ float sh[LKL];
    __shared__ float red[256];

    float lmax = -3.4e38f;
    for (int k = tid; k < kl; k += 256) { float v = srow[k]; sh[k] = v; lmax = fmaxf(lmax, v); }
    red[tid] = lmax; __syncthreads();
    for (int s = 128; s > 0; s >>= 1) { if (tid < s) red[tid] = fmaxf(red[tid], red[tid + s]); __syncthreads(); }
    float m = red[0];
    __syncthreads();

    float lsum = 0.0f;
    for (int k = tid; k < kl; k += 256) { float e = __expf(sh[k] - m); sh[k] = e; lsum += e; }
    red[tid] = lsum; __syncthreads();
    for (int s = 128; s > 0; s >>= 1) { if (tid < s) red[tid] += red[tid + s]; __syncthreads(); }
    float inv = 1.0f / red[0];

    int kmax = ((kl + 63) >> 6) << 6;     // PV only reads up to ceil(kl/64)*64
    for (int k = tid; k < kmax; k += 256) {
        float p = (k < kl) ? sh[k] * inv : 0.0f;
        prow[k] = __float2half(p);
    }
}

// ---------------- GEMM2: O = P V ---------------------------------------------
__global__ __launch_bounds__(256)
void gemm_pv_kernel(float* __restrict__ out, const int* __restrict__ key_len) {
    int b  = blockIdx.z;
    int kl = key_len[b];
    int n0 = blockIdx.x * BN;        // over D (1024/128 = 8)
    int m0 = blockIdx.y * BM;

    extern __shared__ __half sm[];
    int tid = threadIdx.x;

    auto issue = [&](int t) {
        int k0 = t * BKC;
        __half* as = sm + (t % NS) * PV_STAGE_H;
        __half* vs = as + BM * AST;
#pragma unroll
        for (int i = 0; i < 4; i++) {
            int idx = i * 256 + tid;
            int row = idx >> 3, ch = idx & 7;
            cpa16(s2u(as + row * AST + ch * 8),
                  g_P + ((size_t)b * LQL + m0 + row) * LKL + k0 + ch * 8);
            int vrow = idx >> 4, vch = idx & 15;
            cpa16(s2u(vs + vrow * VST + vch * 8),
                  g_V + ((size_t)b * LKL + k0 + vrow) * DDIM + n0 + vch * 8);
        }
        cpcommit();
    };

    float acc[4][4][4];
#pragma unroll
    for (int mt = 0; mt < 4; mt++)
#pragma unroll
        for (int nt = 0; nt < 4; nt++)
#pragma unroll
            for (int j = 0; j < 4; j++) acc[mt][nt][j] = 0.0f;

    int lane = tid & 31, wid = tid >> 5;
    int wm = wid >> 2, wn = wid & 3;
    int arow  = lane & 15;
    int akoff = (lane >> 4) << 3;
    int g     = lane >> 3;
    int vkrow = (lane & 7) + ((g & 1) << 3);
    int vnoff = (g >> 1) << 3;

    int KT = (kl == 0) ? (LKL / BKC) : ((kl + BKC - 1) >> 6);   // P is 0 beyond kl

    issue(0);
    if (KT > 1) issue(1);

    for (int s = 0; s < KT; s++) {
        if (s + 1 < KT) asm volatile("cp.async.wait_group 1;");
        else            asm volatile("cp.async.wait_group 0;");
        __syncthreads();
        if (s + 2 < KT) issue(s + 2);

        const __half* as = sm + (s % NS) * PV_STAGE_H;
        const __half* vs = as + BM * AST;
#pragma unroll
        for (int kk = 0; kk < BKC / 16; kk++) {
            uint32_t a[4][4], bf[4][2];
#pragma unroll
            for (int mt = 0; mt < 4; mt++)
                ldm4(a[mt], s2u(as + (wm * 64 + mt * 16 + arow) * AST + kk * 16 + akoff));
#pragma unroll
            for (int nt2 = 0; nt2 < 2; nt2++) {
                uint32_t r[4];
                ldm4t(r, s2u(vs + (kk * 16 + vkrow) * VST + wn * 32 + nt2 * 16 + vnoff));
                bf[nt2 * 2][0] = r[0];     bf[nt2 * 2][1] = r[1];
                bf[nt2 * 2 + 1][0] = r[2]; bf[nt2 * 2 + 1][1] = r[3];
            }
#pragma unroll
            for (int mt = 0; mt < 4; mt++)
#pragma unroll
                for (int nt = 0; nt < 4; nt++)
                    mma_f16(acc[mt][nt], a[mt], bf[nt][0], bf[nt][1]);
        }
    }

#pragma unroll
    for (int mt = 0; mt < 4; mt++) {
        int r0 = m0 + wm * 64 + mt * 16 + (lane >> 2);
#pragma unroll
        for (int nt = 0; nt < 4; nt++) {
            int c = n0 + wn * 32 + nt * 8 + (lane & 3) * 2;
            float* p0 = out + ((size_t)b * LQL + r0) * DDIM + c;
            *(float2*)p0              = make_float2(acc[mt][nt][0], acc[mt][nt][1]);
            *(float2*)(p0 + 8 * DDIM) = make_float2(acc[mt][nt][2], acc[mt][nt][3]);
        }
    }
}

// ---------------- launch ------------------------------------------------------
extern "C" void kernel_launch(void* const* d_in, const int* in_sizes, int n_in,
                              void* d_out, int out_size) {
    const float* q  = (const float*)d_in[0];
    const float* k  = (const float*)d_in[1];
    const float* v  = (const float*)d_in[2];
    const int*   kl = (const int*)d_in[3];
    float* out = (float*)d_out;

    cudaFuncSetAttribute(gemm_qk_kernel, cudaFuncAttributeMaxDynamicSharedMemorySize, QK_SMEM);
    cudaFuncSetAttribute(gemm_pv_kernel, cudaFuncAttributeMaxDynamicSharedMemorySize, PV_SMEM);

    const int n4 = BB * LQL * DDIM / 4;   // 8388608
    cvt_split_kernel<<<n4 / 256, 256>>>((const float4*)q, 0, n4);
    cvt_split_kernel<<<n4 / 256, 256>>>((const float4*)k, 1, n4);
    cvt_v_kernel   <<<n4 / 256, 256>>>((const float4*)v, n4);

    gemm_qk_kernel<<<dim3(LKL / BN, LQL / BM, BB), 256, QK_SMEM>>>(kl);
    softmax_kernel<<<BB * LQL, 256>>>(kl);
    gemm_pv_kernel<<<dim3(DDIM / BN, LQL / BM, BB), 256, PV_SMEM>>>(out, kl);
}

// round 6
// speedup vs baseline: 1.1702x; 1.1372x over previous
#include <cuda_runtime.h>
#include <cuda_fp16.h>
#include <cstdint>
#include <cstddef>

#define BB   16
#define LQL  2048
#define LKL  2048
#define DDIM 1024

#define BM 128
#define BN 128
#define NS  3

// ---- QK fused-3-pass staging: BK=32 halves (64B rows), 4 tiles per stage ----
#define QK_BK 32
#define QK_TILE_B  8192                      // 128 rows * 64 B
#define QK_STAGE_B (4 * QK_TILE_B)           // Qh,Ql,Kh,Kl
#define QK_SMEM    (NS * QK_STAGE_B)         // 98304 B -> 2 CTAs/SM

// ---- PV staging (unchanged from R5) ----
#define BKC 64
#define AST 72
#define VST 136
#define PV_STAGE_H (BM * AST + 64 * VST)
#define PV_SMEM (NS * PV_STAGE_H * 2)

// ---------------- scratch (static device globals) ---------------------------
__device__ __align__(16) __half g_Qh[(size_t)BB * LQL * DDIM];
__device__ __align__(16) __half g_Ql[(size_t)BB * LQL * DDIM];
__device__ __align__(16) __half g_Kh[(size_t)BB * LKL * DDIM];
__device__ __align__(16) __half g_Kl[(size_t)BB * LKL * DDIM];
__device__ __align__(16) __half g_V [(size_t)BB * LKL * DDIM];
__device__ __align__(16) float  g_S [(size_t)BB * LQL * LKL];
__device__ __align__(16) __half g_P [(size_t)BB * LQL * LKL];

// ---------------- PTX helpers ------------------------------------------------
__device__ __forceinline__ uint32_t s2u(const void* p) {
    return (uint32_t)__cvta_generic_to_shared(p);
}
__device__ __forceinline__ uint32_t sw64(uint32_t o) { return o ^ ((o >> 3) & 0x30); }

__device__ __forceinline__ void ldm4(uint32_t* r, uint32_t a) {
    asm volatile("ldmatrix.sync.aligned.m8n8.x4.shared.b16 {%0,%1,%2,%3},[%4];"
                 : "=r"(r[0]), "=r"(r[1]), "=r"(r[2]), "=r"(r[3]) : "r"(a));
}
__device__ __forceinline__ void ldm4t(uint32_t* r, uint32_t a) {
    asm volatile("ldmatrix.sync.aligned.m8n8.x4.trans.shared.b16 {%0,%1,%2,%3},[%4];"
                 : "=r"(r[0]), "=r"(r[1]), "=r"(r[2]), "=r"(r[3]) : "r"(a));
}
__device__ __forceinline__ void mma_f16(float* c, const uint32_t* a, uint32_t b0, uint32_t b1) {
    asm volatile("mma.sync.aligned.m16n8k16.row.col.f32.f16.f16.f32 "
                 "{%0,%1,%2,%3},{%4,%5,%6,%7},{%8,%9},{%0,%1,%2,%3};"
                 : "+f"(c[0]), "+f"(c[1]), "+f"(c[2]), "+f"(c[3])
                 : "r"(a[0]), "r"(a[1]), "r"(a[2]), "r"(a[3]), "r"(b0), "r"(b1));
}
__device__ __forceinline__ void cpa16(uint32_t s, const void* g) {
    asm volatile("cp.async.cg.shared.global [%0],[%1],16;" :: "r"(s), "l"(g));
}
__device__ __forceinline__ void cpcommit() { asm volatile("cp.async.commit_group;"); }

// ---------------- conversion kernels ----------------------------------------
__global__ void cvt_split_kernel(const float4* __restrict__ x, int which, int n4) {
    int i = blockIdx.x * blockDim.x + threadIdx.x;
    if (i >= n4) return;
    __half* hi = which ? g_Kh : g_Qh;
    __half* lo = which ? g_Kl : g_Ql;
    float4 v = x[i];
    __half h0 = __float2half_rn(v.x), h1 = __float2half_rn(v.y);
    __half h2 = __float2half_rn(v.z), h3 = __float2half_rn(v.w);
    __half l0 = __float2half_rn(v.x - __half2float(h0));
    __half l1 = __float2half_rn(v.y - __half2float(h1));
    __half l2 = __float2half_rn(v.z - __half2float(h2));
    __half l3 = __float2half_rn(v.w - __half2float(h3));
    ((__half2*)hi)[2 * i]     = __halves2half2(h0, h1);
    ((__half2*)hi)[2 * i + 1] = __halves2half2(h2, h3);
    ((__half2*)lo)[2 * i]     = __halves2half2(l0, l1);
    ((__half2*)lo)[2 * i + 1] = __halves2half2(l2, l3);
}

__global__ void cvt_v_kernel(const float4* __restrict__ x, int n4) {
    int i = blockIdx.x * blockDim.x + threadIdx.x;
    if (i >= n4) return;
    float4 v = x[i];
    ((__half2*)g_V)[2 * i]     = __halves2half2(__float2half_rn(v.x), __float2half_rn(v.y));
    ((__half2*)g_V)[2 * i + 1] = __halves2half2(__float2half_rn(v.z), __float2half_rn(v.w));
}

// ---- GEMM1: S = Q K^T, fused hi/lo 3-pass, BK=32, 4 tiles/stage -------------
__global__ __launch_bounds__(256, 2)
void gemm_qk_kernel(const int* __restrict__ key_len) {
    int b  = blockIdx.z;
    int kl = key_len[b];
    int n0 = blockIdx.x * BN;
    if (n0 >= kl) return;            // masked tile (also kl==0): softmax never reads it
    int m0 = blockIdx.y * BM;

    extern __shared__ __half sm[];
    uint32_t smb = s2u(sm);

    int tid = threadIdx.x;
    const __half* srcQh = g_Qh + ((size_t)b * LQL + m0) * DDIM;
    const __half* srcQl = g_Ql + ((size_t)b * LQL + m0) * DDIM;
    const __half* srcKh = g_Kh + ((size_t)b * LKL + n0) * DDIM;
    const __half* srcKl = g_Kl + ((size_t)b * LKL + n0) * DDIM;

    // per-thread load coords: tile is 128 rows x 64B; 512 chunks of 16B; 2/thread
    int lrow0 = tid >> 2,  lc0 = tid & 3;           // chunks 0..255
    int lrow1 = (256 + tid) >> 2;                   // chunks 256..511 (same c pattern)
    uint32_t sOff0 = sw64(lrow0 * 64 + lc0 * 16);
    uint32_t sOff1 = sw64(lrow1 * 64 + lc0 * 16);

    auto issue = [&](int t) {
        int k0 = t * QK_BK;
        uint32_t st = smb + (t % NS) * QK_STAGE_B;
        const __half* s0q = srcQh + k0 + lc0 * 8;
        const __half* s0l = srcQl + k0 + lc0 * 8;
        const __half* s0k = srcKh + k0 + lc0 * 8;
        const __half* s0m = srcKl + k0 + lc0 * 8;
        cpa16(st + sOff0,                 s0q + (size_t)lrow0 * DDIM);
        cpa16(st + sOff1,                 s0q + (size_t)lrow1 * DDIM);
        cpa16(st + QK_TILE_B + sOff0,     s0l + (size_t)lrow0 * DDIM);
        cpa16(st + QK_TILE_B + sOff1,     s0l + (size_t)lrow1 * DDIM);
        cpa16(st + 2 * QK_TILE_B + sOff0, s0k + (size_t)lrow0 * DDIM);
        cpa16(st + 2 * QK_TILE_B + sOff1, s0k + (size_t)lrow1 * DDIM);
        cpa16(st + 3 * QK_TILE_B + sOff0, s0m + (size_t)lrow0 * DDIM);
        cpa16(st + 3 * QK_TILE_B + sOff1, s0m + (size_t)lrow1 * DDIM);
        cpcommit();
    };

    float acc[4][4][4];
#pragma unroll
    for (int mt = 0; mt < 4; mt++)
#pragma unroll
        for (int nt = 0; nt < 4; nt++)
#pragma unroll
            for (int j = 0; j < 4; j++) acc[mt][nt][j] = 0.0f;

    int lane = tid & 31, wid = tid >> 5;
    int wm = wid >> 2, wn = wid & 3;          // 2x4 warp grid, warp tile 64x32
    int arow = lane & 15, ac = lane >> 4;     // A: rows 0..15, chunk 0/1
    int g    = lane >> 3;
    int brow = (lane & 7) + ((g >> 1) << 3);  // B rows
    int bc   = g & 1;

    const int KT = DDIM / QK_BK;              // 32
    issue(0);
    issue(1);

    for (int s = 0; s < KT; s++) {
        if (s + 1 < KT) asm volatile("cp.async.wait_group 1;");
        else            asm volatile("cp.async.wait_group 0;");
        __syncthreads();
        if (s + 2 < KT) issue(s + 2);

        uint32_t st = smb + (s % NS) * QK_STAGE_B;
        uint32_t tQh = st, tQl = st + QK_TILE_B;
        uint32_t tKh = st + 2 * QK_TILE_B, tKl = st + 3 * QK_TILE_B;

#pragma unroll
        for (int kk = 0; kk < 2; kk++) {
            uint32_t a[4][4], bh[4][2], bl[4][2];
            // B fragments (Kh, Kl)
#pragma unroll
            for (int nt2 = 0; nt2 < 2; nt2++) {
                uint32_t off = sw64((wn * 32 + nt2 * 16 + brow) * 64 + (kk * 2 + bc) * 16);
                uint32_t r[4];
                ldm4(r, tKh + off);
                bh[nt2 * 2][0] = r[0];     bh[nt2 * 2][1] = r[1];
                bh[nt2 * 2 + 1][0] = r[2]; bh[nt2 * 2 + 1][1] = r[3];
                ldm4(r, tKl + off);
                bl[nt2 * 2][0] = r[0];     bl[nt2 * 2][1] = r[1];
                bl[nt2 * 2 + 1][0] = r[2]; bl[nt2 * 2 + 1][1] = r[3];
            }
            // A = Qh : acc += Qh*Kh + Qh*Kl
#pragma unroll
            for (int mt = 0; mt < 4; mt++) {
                uint32_t off = sw64((wm * 64 + mt * 16 + arow) * 64 + (kk * 2 + ac) * 16);
                ldm4(a[mt], tQh + off);
            }
#pragma unroll
            for (int mt = 0; mt < 4; mt++)
#pragma unroll
                for (int nt = 0; nt < 4; nt++)
                    mma_f16(acc[mt][nt], a[mt], bh[nt][0], bh[nt][1]);
#pragma unroll
            for (int mt = 0; mt < 4; mt++)
#pragma unroll
                for (int nt = 0; nt < 4; nt++)
                    mma_f16(acc[mt][nt], a[mt], bl[nt][0], bl[nt][1]);
            // A = Ql : acc += Ql*Kh
#pragma unroll
            for (int mt = 0; mt < 4; mt++) {
                uint32_t off = sw64((wm * 64 + mt * 16 + arow) * 64 + (kk * 2 + ac) * 16);
                ldm4(a[mt], tQl + off);
            }
#pragma unroll
            for (int mt = 0; mt < 4; mt++)
#pragma unroll
                for (int nt = 0; nt < 4; nt++)
                    mma_f16(acc[mt][nt], a[mt], bh[nt][0], bh[nt][1]);
        }
    }

#pragma unroll
    for (int mt = 0; mt < 4; mt++) {
        int r0 = m0 + wm * 64 + mt * 16 + (lane >> 2);
#pragma unroll
        for (int nt = 0; nt < 4; nt++) {
            int c = n0 + wn * 32 + nt * 8 + (lane & 3) * 2;
            float* p0 = g_S + ((size_t)b * LQL + r0) * LKL + c;
            *(float2*)p0             = make_float2(acc[mt][nt][0], acc[mt][nt][1]);
            *(float2*)(p0 + 8 * LKL) = make_float2(acc[mt][nt][2], acc[mt][nt][3]);
        }
    }
}

// ---------------- row softmax with key_len mask ------------------------------
__global__ void softmax_kernel(const int* __restrict__ key_len) {
    int row = blockIdx.x;            // b*LQ + q
    int b = row >> 11;
    int kl = key_len[b];
    __half* prow = g_P + (size_t)row * LKL;
    int tid = threadIdx.x;

    if (kl == 0) {                   // all masked -> uniform softmax (matches jax exactly)
        __half2 u2 = __halves2half2(__float2half(1.0f / 2048.0f), __float2half(1.0f / 2048.0f));
        __half2* p2 = (__half2*)prow;
        for (int i = tid; i < LKL / 2; i += 256) p2[i] = u2;
        return;
    }

    const float* srow = g_S + (size_t)row * LKL;
    __shared__ float sh[LKL];
    __shared__ float red[256];

    float lmax = -3.4e38f;
    for (int k = tid; k < kl; k += 256) { float v = srow[k]; sh[k] = v; lmax = fmaxf(lmax, v); }
    red[tid] = lmax; __syncthreads();
    for (int s = 128; s > 0; s >>= 1) { if (tid < s) red[tid] = fmaxf(red[tid], red[tid + s]); __syncthreads(); }
    float m = red[0];
    __syncthreads();

    float lsum = 0.0f;
    for (int k = tid; k < kl; k += 256) { float e = __expf(sh[k] - m); sh[k] = e; lsum += e; }
    red[tid] = lsum; __syncthreads();
    for (int s = 128; s > 0; s >>= 1) { if (tid < s) red[tid] += red[tid + s]; __syncthreads(); }
    float inv = 1.0f / red[0];

    int kmax = ((kl + 63) >> 6) << 6;     // PV only reads up to ceil(kl/64)*64
    for (int k = tid; k < kmax; k += 256) {
        float p = (k < kl) ? sh[k] * inv : 0.0f;
        prow[k] = __float2half(p);
    }
}

// ---------------- GEMM2: O = P V ---------------------------------------------
__global__ __launch_bounds__(256)
void gemm_pv_kernel(float* __restrict__ out, const int* __restrict__ key_len) {
    int b  = blockIdx.z;
    int kl = key_len[b];
    int n0 = blockIdx.x * BN;        // over D (1024/128 = 8)
    int m0 = blockIdx.y * BM;

    extern __shared__ __half sm[];
    int tid = threadIdx.x;

    auto issue = [&](int t) {
        int k0 = t * BKC;
        __half* as = sm + (t % NS) * PV_STAGE_H;
        __half* vs = as + BM * AST;
#pragma unroll
        for (int i = 0; i < 4; i++) {
            int idx = i * 256 + tid;
            int row = idx >> 3, ch = idx & 7;
            cpa16(s2u(as + row * AST + ch * 8),
                  g_P + ((size_t)b * LQL + m0 + row) * LKL + k0 + ch * 8);
            int vrow = idx >> 4, vch = idx & 15;
            cpa16(s2u(vs + vrow * VST + vch * 8),
                  g_V + ((size_t)b * LKL + k0 + vrow) * DDIM + n0 + vch * 8);
        }
        cpcommit();
    };

    float acc[4][4][4];
#pragma unroll
    for (int mt = 0; mt < 4; mt++)
#pragma unroll
        for (int nt = 0; nt < 4; nt++)
#pragma unroll
            for (int j = 0; j < 4; j++) acc[mt][nt][j] = 0.0f;

    int lane = tid & 31, wid = tid >> 5;
    int wm = wid >> 2, wn = wid & 3;
    int arow  = lane & 15;
    int akoff = (lane >> 4) << 3;
    int g     = lane >> 3;
    int vkrow = (lane & 7) + ((g & 1) << 3);
    int vnoff = (g >> 1) << 3;

    int KT = (kl == 0) ? (LKL / BKC) : ((kl + BKC - 1) >> 6);   // P is 0 beyond kl

    issue(0);
    if (KT > 1) issue(1);

    for (int s = 0; s < KT; s++) {
        if (s + 1 < KT) asm volatile("cp.async.wait_group 1;");
        else            asm volatile("cp.async.wait_group 0;");
        __syncthreads();
        if (s + 2 < KT) issue(s + 2);

        const __half* as = sm + (s % NS) * PV_STAGE_H;
        const __half* vs = as + BM * AST;
#pragma unroll
        for (int kk = 0; kk < BKC / 16; kk++) {
            uint32_t a[4][4], bf[4][2];
#pragma unroll
            for (int mt = 0; mt < 4; mt++)
                ldm4(a[mt], s2u(as + (wm * 64 + mt * 16 + arow) * AST + kk * 16 + akoff));
#pragma unroll
            for (int nt2 = 0; nt2 < 2; nt2++) {
                uint32_t r[4];
                ldm4t(r, s2u(vs + (kk * 16 + vkrow) * VST + wn * 32 + nt2 * 16 + vnoff));
                bf[nt2 * 2][0] = r[0];     bf[nt2 * 2][1] = r[1];
                bf[nt2 * 2 + 1][0] = r[2]; bf[nt2 * 2 + 1][1] = r[3];
            }
#pragma unroll
            for (int mt = 0; mt < 4; mt++)
#pragma unroll
                for (int nt = 0; nt < 4; nt++)
                    mma_f16(acc[mt][nt], a[mt], bf[nt][0], bf[nt][1]);
        }
    }

#pragma unroll
    for (int mt = 0; mt < 4; mt++) {
        int r0 = m0 + wm * 64 + mt * 16 + (lane >> 2);
#pragma unroll
        for (int nt = 0; nt < 4; nt++) {
            int c = n0 + wn * 32 + nt * 8 + (lane & 3) * 2;
            float* p0 = out + ((size_t)b * LQL + r0) * DDIM + c;
            *(float2*)p0              = make_float2(acc[mt][nt][0], acc[mt][nt][1]);
            *(float2*)(p0 + 8 * DDIM) = make_float2(acc[mt][nt][2], acc[mt][nt][3]);
        }
    }
}

// ---------------- launch ------------------------------------------------------
extern "C" void kernel_launch(void* const* d_in, const int* in_sizes, int n_in,
                              void* d_out, int out_size) {
    const float* q  = (const float*)d_in[0];
    const float* k  = (const float*)d_in[1];
    const float* v  = (const float*)d_in[2];
    const int*   kl = (const int*)d_in[3];
    float* out = (float*)d_out;

    cudaFuncSetAttribute(gemm_qk_kernel, cudaFuncAttributeMaxDynamicSharedMemorySize, QK_SMEM);
    cudaFuncSetAttribute(gemm_pv_kernel, cudaFuncAttributeMaxDynamicSharedMemorySize, PV_SMEM);

    const int n4 = BB * LQL * DDIM / 4;   // 8388608
    cvt_split_kernel<<<n4 / 256, 256>>>((const float4*)q, 0, n4);
    cvt_split_kernel<<<n4 / 256, 256>>>((const float4*)k, 1, n4);
    cvt_v_kernel   <<<n4 / 256, 256>>>((const float4*)v, n4);

    gemm_qk_kernel<<<dim3(LKL / BN, LQL / BM, BB), 256, QK_SMEM>>>(kl);
    softmax_kernel<<<BB * LQL, 256>>>(kl);
    gemm_pv_kernel<<<dim3(DDIM / BN, LQL / BM, BB), 256, PV_SMEM>>>(out, kl);
}